// round 5
// baseline (speedup 1.0000x reference)
#include <cuda_runtime.h>
#include <math.h>

#define NB   8192
#define CHK  1024
#define NCH  8            // NB / CHK = grid of prep kernel
#define QG   128          // query blocks
#define QT   256          // query threads (QG * QT/4 rows... 128*64 = 8192 rows)

__device__ __align__(16) float g_risk[NB];
__device__ __align__(16) float g_tsrt[NB];
__device__ __align__(16) float g_pe[NB];
__device__ float g_nll[NCH];
__device__ float g_per[QG];
__device__ int   g_cnt[QG];
__device__ int   g_ticket;

// ---------------- Kernel 1: rows + register bitonic sort + prefix sum ----------------
extern "C" __global__ void __launch_bounds__(CHK, 1)
surv_prep_kernel(const float* __restrict__ outputs,
                 const int* __restrict__ y,
                 const float* __restrict__ t,
                 const int* __restrict__ c)
{
    __shared__ float ts[CHK];
    __shared__ float es[CHK];
    __shared__ float wsum[32];
    const int tid  = threadIdx.x;
    const int blk  = blockIdx.x;
    const int lane = tid & 31;
    const int wid  = tid >> 5;
    const int r    = blk * CHK + tid;
    const float EPSC = 1e-7f;

    // ---- per-row risk / e / NLL ----
    float4 o4 = ((const float4*)outputs)[r];
    float o[4] = {o4.x, o4.y, o4.z, o4.w};
    float hz[4], Sc[4];
    float Sp = 1.f, Ssum = 0.f;
    #pragma unroll
    for (int k = 0; k < 4; k++) {
        float h = 1.f / (1.f + __expf(-o[k]));
        hz[k] = h;
        Sp *= (1.f - h);
        Sc[k] = Sp;
        Ssum += Sp;
    }
    float risk = -Ssum;
    int yi = y[r];
    float s_prev = fmaxf((yi == 0) ? 1.f : Sc[yi - 1], EPSC);
    float h_this = fmaxf(hz[yi], EPSC);
    float s_this = fmaxf(Sc[yi], EPSC);
    float cf = (float)c[r];
    float nll = -(1.f - cf) * (__logf(s_prev) + __logf(h_this))
                - cf * __logf(s_this);
    g_risk[r] = risk;

    float my_t = t[r];
    float my_e = __expf(risk);

    // ---- NLL reduction (fixed order: butterfly + sequential warp sums) ----
    #pragma unroll
    for (int off = 16; off > 0; off >>= 1)
        nll += __shfl_xor_sync(0xffffffffu, nll, off);
    if (lane == 0) wsum[wid] = nll;
    __syncthreads();
    if (tid == 0) {
        float s = 0.f;
        #pragma unroll
        for (int w = 0; w < 32; w++) s += wsum[w];
        g_nll[blk] = s;
    }
    __syncthreads();   // wsum reused below

    // ---- bitonic sort descending by t (payload e), 1 elem/thread ----
    for (int k = 2; k <= CHK; k <<= 1) {
        const bool desc = ((tid & k) == 0);
        int j = k >> 1;
        // cross-warp steps via smem
        for (; j >= 32; j >>= 1) {
            ts[tid] = my_t; es[tid] = my_e;
            __syncthreads();
            int p = tid ^ j;
            float ot = ts[p], oe = es[p];
            bool i_lower = ((tid & j) == 0);
            bool my_g = (my_t > ot) || ((my_t == ot) && i_lower);
            if (my_g != (i_lower == desc)) { my_t = ot; my_e = oe; }
            __syncthreads();
        }
        // intra-warp steps via shfl (no barriers)
        for (; j > 0; j >>= 1) {
            float ot = __shfl_xor_sync(0xffffffffu, my_t, j);
            float oe = __shfl_xor_sync(0xffffffffu, my_e, j);
            bool i_lower = ((tid & j) == 0);
            bool my_g = (my_t > ot) || ((my_t == ot) && i_lower);
            if (my_g != (i_lower == desc)) { my_t = ot; my_e = oe; }
        }
    }

    // ---- inclusive prefix sum of sorted e (2-level shfl scan) ----
    float v = my_e;
    #pragma unroll
    for (int off = 1; off < 32; off <<= 1) {
        float n = __shfl_up_sync(0xffffffffu, v, off);
        if (lane >= off) v += n;
    }
    if (lane == 31) wsum[wid] = v;
    __syncthreads();
    if (wid == 0) {
        float w = wsum[lane];
        #pragma unroll
        for (int off = 1; off < 32; off <<= 1) {
            float n = __shfl_up_sync(0xffffffffu, w, off);
            if (lane >= off) w += n;
        }
        wsum[lane] = w;
    }
    __syncthreads();
    float pe = v + ((wid > 0) ? wsum[wid - 1] : 0.f);

    g_tsrt[r] = my_t;
    g_pe[r]   = pe;
}

// ---------------- Kernel 2: rank queries (4 thr/row) + ticket finalize ----------------
extern "C" __global__ void __launch_bounds__(QT)
surv_query_kernel(const float* __restrict__ t,
                  const int* __restrict__ c,
                  float* __restrict__ out)
{
    extern __shared__ float sm[];       // 64 KB: t table + prefix-e table
    float* t_s  = sm;                   // [NB]
    float* pe_s = sm + NB;              // [NB]
    __shared__ float redf[QT];
    __shared__ int   redi[QT];
    __shared__ int   is_last;

    const int tid = threadIdx.x;
    const int blk = blockIdx.x;

    #pragma unroll
    for (int i = tid; i < NB / 4; i += QT) {
        ((float4*)t_s)[i]  = ((const float4*)g_tsrt)[i];
        ((float4*)pe_s)[i] = ((const float4*)g_pe)[i];
    }

    const int row = blk * (QT / 4) + (tid >> 2);
    const int q   = tid & 3;
    const float ti = t[row];
    __syncthreads();

    // 2 interleaved binary searches over chunks w = q*2 + k
    int cw[2] = {0, 0};
    #pragma unroll
    for (int s = CHK / 2; s > 0; s >>= 1) {
        #pragma unroll
        for (int k = 0; k < 2; k++)
            cw[k] += (t_s[(q * 2 + k) * CHK + cw[k] + s - 1] > ti) ? s : 0;
    }
    #pragma unroll
    for (int k = 0; k < 2; k++)
        cw[k] += (t_s[(q * 2 + k) * CHK + cw[k]] > ti) ? 1 : 0;

    float sum = 0.f;
    int   cnt = 0;
    #pragma unroll
    for (int k = 0; k < 2; k++) {
        if (cw[k] > 0) {
            sum += pe_s[(q * 2 + k) * CHK + cw[k] - 1];
            cnt += cw[k];
        }
    }
    // combine the 4 lanes of this row (lanes differ only in bits 0-1)
    sum += __shfl_xor_sync(0xffffffffu, sum, 1);
    sum += __shfl_xor_sync(0xffffffffu, sum, 2);
    cnt += __shfl_xor_sync(0xffffffffu, cnt, 1);
    cnt += __shfl_xor_sync(0xffffffffu, cnt, 2);

    float per = 0.f;
    int   cv  = 0;
    if (q == 0) {
        bool valid = (c[row] == 0) && (cnt > 0);
        if (valid) {
            per = __logf(sum) - g_risk[row];
            cv  = 1;
        }
    }
    redf[tid] = per;
    redi[tid] = cv;
    __syncthreads();
    for (int off = QT >> 1; off > 0; off >>= 1) {
        if (tid < off) {
            redf[tid] += redf[tid + off];
            redi[tid] += redi[tid + off];
        }
        __syncthreads();
    }
    if (tid == 0) {
        g_per[blk] = redf[0];
        g_cnt[blk] = redi[0];
        __threadfence();
        int tk = atomicAdd(&g_ticket, 1);
        is_last = (tk == QG - 1) ? 1 : 0;
    }
    __syncthreads();

    if (is_last && tid == 0) {
        __threadfence();
        float per_t = 0.f, nll_t = 0.f;
        int cnt_t = 0;
        #pragma unroll 8
        for (int b = 0; b < QG; b++) { per_t += g_per[b]; cnt_t += g_cnt[b]; }
        #pragma unroll
        for (int b = 0; b < NCH; b++) nll_t += g_nll[b];
        float rank = (cnt_t > 0) ? (per_t / (float)cnt_t) : 0.f;
        out[0] = nll_t / (float)NB + 0.5f * rank;
        g_ticket = 0;   // self-reset for graph replay
    }
}

extern "C" void kernel_launch(void* const* d_in, const int* in_sizes, int n_in,
                              void* d_out, int out_size)
{
    const float* outputs = (const float*)d_in[0];
    const int*   y       = (const int*)d_in[1];
    const float* t       = (const float*)d_in[2];
    const int*   c       = (const int*)d_in[3];
    float*       out     = (float*)d_out;

    size_t smem2 = (size_t)NB * 2 * sizeof(float);   // 64 KB
    cudaFuncSetAttribute(surv_query_kernel,
                         cudaFuncAttributeMaxDynamicSharedMemorySize, (int)smem2);

    surv_prep_kernel<<<NCH, CHK>>>(outputs, y, t, c);
    surv_query_kernel<<<QG, QT, smem2>>>(t, c, out);
}

// round 6
// speedup vs baseline: 1.3891x; 1.3891x over previous
#include <cuda_runtime.h>
#include <math.h>

#define NB   8192
#define CHK  1024
#define NCH  8            // NB / CHK = prep grid
#define QG   32           // query blocks
#define QT   1024         // query threads: 32*1024/8192 = 4 threads per row

__device__ __align__(16) float g_risk[NB];
__device__ __align__(16) float g_tsrt[NB];
__device__ __align__(16) float g_pe[NB];
__device__ float g_nll[NCH];
__device__ float g_per[QG];
__device__ int   g_cnt[QG];
__device__ int   g_ticket;

// ---------------- Kernel 1: rows + hybrid bitonic sort + prefix sum ----------------
extern "C" __global__ void __launch_bounds__(CHK, 1)
surv_prep_kernel(const float* __restrict__ outputs,
                 const int* __restrict__ y,
                 const float* __restrict__ t,
                 const int* __restrict__ c)
{
    __shared__ float tsA[CHK], esA[CHK];
    __shared__ float tsB[CHK], esB[CHK];
    __shared__ float wsum[32];
    const int tid  = threadIdx.x;
    const int blk  = blockIdx.x;
    const int lane = tid & 31;
    const int wid  = tid >> 5;
    const int r    = blk * CHK + tid;
    const float EPSC = 1e-7f;

    // ---- per-row risk / e / NLL ----
    float4 o4 = ((const float4*)outputs)[r];
    float o[4] = {o4.x, o4.y, o4.z, o4.w};
    float hz[4], Sc[4];
    float Sp = 1.f, Ssum = 0.f;
    #pragma unroll
    for (int k = 0; k < 4; k++) {
        float h = 1.f / (1.f + __expf(-o[k]));
        hz[k] = h;
        Sp *= (1.f - h);
        Sc[k] = Sp;
        Ssum += Sp;
    }
    float risk = -Ssum;
    int yi = y[r];
    float s_prev = fmaxf((yi == 0) ? 1.f : Sc[yi - 1], EPSC);
    float h_this = fmaxf(hz[yi], EPSC);
    float s_this = fmaxf(Sc[yi], EPSC);
    float cf = (float)c[r];
    float nll = -(1.f - cf) * (__logf(s_prev) + __logf(h_this))
                - cf * __logf(s_this);
    g_risk[r] = risk;

    float my_t = t[r];
    float my_e = __expf(risk);

    // ---- NLL reduction: warp butterfly + warp0 combine ----
    #pragma unroll
    for (int off = 16; off > 0; off >>= 1)
        nll += __shfl_xor_sync(0xffffffffu, nll, off);
    if (lane == 0) wsum[wid] = nll;
    __syncthreads();
    if (wid == 0) {
        float s = wsum[lane];
        #pragma unroll
        for (int off = 16; off > 0; off >>= 1)
            s += __shfl_xor_sync(0xffffffffu, s, off);
        if (lane == 0) g_nll[blk] = s;
    }
    __syncthreads();

    // ---- bitonic sort descending by t (payload e), 1 elem/thread ----
    int buf = 0;
    for (int k = 2; k <= CHK; k <<= 1) {
        const bool desc = ((tid & k) == 0);
        int j = k >> 1;
        // cross-warp steps via ping-pong smem (1 barrier per step)
        for (; j >= 32; j >>= 1) {
            float* T = buf ? tsB : tsA;
            float* E = buf ? esB : esA;
            T[tid] = my_t; E[tid] = my_e;
            __syncthreads();
            int p = tid ^ j;
            float ot = T[p], oe = E[p];
            bool i_lower = ((tid & j) == 0);
            bool my_g = (my_t > ot) || ((my_t == ot) && i_lower);
            if (my_g != (i_lower == desc)) { my_t = ot; my_e = oe; }
            buf ^= 1;
        }
        // intra-warp steps via shfl (no barriers)
        for (; j > 0; j >>= 1) {
            float ot = __shfl_xor_sync(0xffffffffu, my_t, j);
            float oe = __shfl_xor_sync(0xffffffffu, my_e, j);
            bool i_lower = ((tid & j) == 0);
            bool my_g = (my_t > ot) || ((my_t == ot) && i_lower);
            if (my_g != (i_lower == desc)) { my_t = ot; my_e = oe; }
        }
    }

    // ---- inclusive prefix sum of sorted e (2-level shfl scan) ----
    __syncthreads();    // protect wsum reuse
    float v = my_e;
    #pragma unroll
    for (int off = 1; off < 32; off <<= 1) {
        float n = __shfl_up_sync(0xffffffffu, v, off);
        if (lane >= off) v += n;
    }
    if (lane == 31) wsum[wid] = v;
    __syncthreads();
    if (wid == 0) {
        float w = wsum[lane];
        #pragma unroll
        for (int off = 1; off < 32; off <<= 1) {
            float n = __shfl_up_sync(0xffffffffu, w, off);
            if (lane >= off) w += n;
        }
        wsum[lane] = w;
    }
    __syncthreads();
    float pe = v + ((wid > 0) ? wsum[wid - 1] : 0.f);

    g_tsrt[r] = my_t;
    g_pe[r]   = pe;
}

// ---------------- Kernel 2: rank queries (4 thr/row, 32 warps/blk) ----------------
extern "C" __global__ void __launch_bounds__(QT, 1)
surv_query_kernel(const float* __restrict__ t,
                  const int* __restrict__ c,
                  float* __restrict__ out)
{
    extern __shared__ float t_s[];        // [NB] 32 KB, t table only
    __shared__ float wper[32];
    __shared__ int   wcnt[32];
    __shared__ int   is_last;

    const int tid  = threadIdx.x;
    const int blk  = blockIdx.x;
    const int lane = tid & 31;
    const int wid  = tid >> 5;

    #pragma unroll
    for (int i = tid; i < NB / 4; i += QT)
        ((float4*)t_s)[i] = ((const float4*)g_tsrt)[i];

    const int row = blk * (QT / 4) + (tid >> 2);
    const int q   = tid & 3;
    const float ti = t[row];
    __syncthreads();

    // 2 interleaved binary searches over chunks w = q*2 + k
    int cw0 = 0, cw1 = 0;
    const int b0 = (q * 2 + 0) * CHK;
    const int b1 = (q * 2 + 1) * CHK;
    #pragma unroll
    for (int s = CHK / 2; s > 0; s >>= 1) {
        cw0 += (t_s[b0 + cw0 + s - 1] > ti) ? s : 0;
        cw1 += (t_s[b1 + cw1 + s - 1] > ti) ? s : 0;
    }
    cw0 += (t_s[b0 + cw0] > ti) ? 1 : 0;
    cw1 += (t_s[b1 + cw1] > ti) ? 1 : 0;

    float sum = 0.f;
    int   cnt = cw0 + cw1;
    if (cw0 > 0) sum += __ldg(&g_pe[b0 + cw0 - 1]);
    if (cw1 > 0) sum += __ldg(&g_pe[b1 + cw1 - 1]);

    // combine the 4 lanes of this row (lanes differ only in bits 0-1)
    sum += __shfl_xor_sync(0xffffffffu, sum, 1);
    sum += __shfl_xor_sync(0xffffffffu, sum, 2);
    cnt += __shfl_xor_sync(0xffffffffu, cnt, 1);
    cnt += __shfl_xor_sync(0xffffffffu, cnt, 2);

    float per = 0.f;
    int   cv  = 0;
    if (q == 0) {
        bool valid = (c[row] == 0) && (cnt > 0);
        if (valid) {
            per = __logf(sum) - __ldg(&g_risk[row]);
            cv  = 1;
        }
    }

    // warp butterfly + cross-warp reduce
    #pragma unroll
    for (int off = 16; off > 0; off >>= 1) {
        per += __shfl_xor_sync(0xffffffffu, per, off);
        cv  += __shfl_xor_sync(0xffffffffu, cv, off);
    }
    if (lane == 0) { wper[wid] = per; wcnt[wid] = cv; }
    __syncthreads();
    if (wid == 0) {
        float p2 = wper[lane];
        int   c2 = wcnt[lane];
        #pragma unroll
        for (int off = 16; off > 0; off >>= 1) {
            p2 += __shfl_xor_sync(0xffffffffu, p2, off);
            c2 += __shfl_xor_sync(0xffffffffu, c2, off);
        }
        if (lane == 0) {
            g_per[blk] = p2;
            g_cnt[blk] = c2;
            __threadfence();
            int tk = atomicAdd(&g_ticket, 1);
            is_last = (tk == QG - 1) ? 1 : 0;
        }
    }
    __syncthreads();

    if (is_last && tid == 0) {
        __threadfence();
        float per_t = 0.f, nll_t = 0.f;
        int cnt_t = 0;
        #pragma unroll
        for (int b = 0; b < QG; b++) { per_t += g_per[b]; cnt_t += g_cnt[b]; }
        #pragma unroll
        for (int b = 0; b < NCH; b++) nll_t += g_nll[b];
        float rank = (cnt_t > 0) ? (per_t / (float)cnt_t) : 0.f;
        out[0] = nll_t / (float)NB + 0.5f * rank;
        g_ticket = 0;   // self-reset for graph replay
    }
}

extern "C" void kernel_launch(void* const* d_in, const int* in_sizes, int n_in,
                              void* d_out, int out_size)
{
    const float* outputs = (const float*)d_in[0];
    const int*   y       = (const int*)d_in[1];
    const float* t       = (const float*)d_in[2];
    const int*   c       = (const int*)d_in[3];
    float*       out     = (float*)d_out;

    size_t smem2 = (size_t)NB * sizeof(float);   // 32 KB
    cudaFuncSetAttribute(surv_query_kernel,
                         cudaFuncAttributeMaxDynamicSharedMemorySize, (int)smem2);

    surv_prep_kernel<<<NCH, CHK>>>(outputs, y, t, c);
    surv_query_kernel<<<QG, QT, smem2>>>(t, c, out);
}

// round 8
// speedup vs baseline: 1.7215x; 1.2393x over previous
#include <cuda_runtime.h>
#include <math.h>

#define NB    8192
#define GRID  32
#define NT    1024
#define RPB   256          // rows per block = chunk size
#define CHK   256
#define TPAD  257          // padded chunk stride in smem floats

__device__ __align__(16) float g_tsrt[NB];
__device__ __align__(16) float g_pe[NB];
__device__ float g_nll[GRID];
__device__ float g_per[GRID];
__device__ int   g_cnt[GRID];
__device__ int   g_ticket;
__device__ unsigned g_bcount;
__device__ volatile unsigned g_bgen;

#define BAR256() asm volatile("bar.sync 1, 256;" ::: "memory")

__device__ __forceinline__ void grid_bar() {
    __threadfence();            // release: this thread's writes visible device-wide
    __syncthreads();
    if (threadIdx.x == 0) {
        unsigned gen = g_bgen;
        if (atomicAdd(&g_bcount, 1u) == GRID - 1) {
            g_bcount = 0;
            __threadfence();
            g_bgen = gen + 1;
        } else {
            while (g_bgen == gen) { __nanosleep(32); }
        }
        __threadfence();        // acquire: order spin-observation before later reads
    }
    __syncthreads();
}

extern "C" __global__ void __launch_bounds__(NT, 1)
surv_one_kernel(const float* __restrict__ outputs,
                const int* __restrict__ y,
                const float* __restrict__ t,
                const int* __restrict__ c,
                float* __restrict__ out)
{
    __shared__ __align__(16) char sbuf[38016];
    float* se    = (float*)(sbuf);            // [256] e per local row
    float* srisk = (float*)(sbuf + 1024);     // [256]
    int*   sc    = (int*)  (sbuf + 2048);     // [256]
    int*   sidx  = (int*)  (sbuf + 3072);     // [256] sorted-pos -> local row
    float* st_s  = (float*)(sbuf + 4096);     // [256] sorted t
    // phase-B sort ping-pong buffers (overlap t_tab; B finishes before C)
    float* kbuf0 = (float*)(sbuf + 5120);
    int*   ibuf0 = (int*)  (sbuf + 6144);
    float* kbuf1 = (float*)(sbuf + 7168);
    int*   ibuf1 = (int*)  (sbuf + 8192);
    // phase-C global t table, padded stride
    float* t_tab = (float*)(sbuf + 5120);     // [32 * 257]
    __shared__ float wpart[8];
    __shared__ float bredf[32];
    __shared__ int   bredi[32];
    __shared__ int   is_last;

    const int tid  = threadIdx.x;
    const int blk  = blockIdx.x;
    const int lane = tid & 31;
    const int wid  = tid >> 5;
    const float EPSC = 1e-7f;

    // ================= Phase A + B: first 8 warps only =================
    if (tid < RPB) {
        const int r = blk * RPB + tid;

        float4 o4 = ((const float4*)outputs)[r];
        float o[4] = {o4.x, o4.y, o4.z, o4.w};
        float hz[4], Sc[4];
        float Sp = 1.f, Ssum = 0.f;
        #pragma unroll
        for (int k = 0; k < 4; k++) {
            float h = 1.f / (1.f + __expf(-o[k]));
            hz[k] = h;
            Sp *= (1.f - h);
            Sc[k] = Sp;
            Ssum += Sp;
        }
        float risk = -Ssum;
        int yi = y[r];
        float s_prev = fmaxf((yi == 0) ? 1.f : Sc[yi - 1], EPSC);
        float h_this = fmaxf(hz[yi], EPSC);
        float s_this = fmaxf(Sc[yi], EPSC);
        float cf = (float)c[r];
        float nll = -(1.f - cf) * (__logf(s_prev) + __logf(h_this))
                    - cf * __logf(s_this);

        se[tid]    = __expf(risk);
        srisk[tid] = risk;
        sc[tid]    = c[r];

        // NLL reduction over 8 warps
        #pragma unroll
        for (int off = 16; off > 0; off >>= 1)
            nll += __shfl_xor_sync(0xffffffffu, nll, off);
        if (lane == 0) wpart[wid] = nll;
        BAR256();
        if (tid == 0) {
            float s = 0.f;
            #pragma unroll
            for (int w = 0; w < 8; w++) s += wpart[w];
            g_nll[blk] = s;
        }

        // ---- bitonic sort of 256 (key t desc, payload local idx) ----
        float kt = t[r];
        int   idx = tid;
        int buf = 0;
        for (int k = 2; k <= RPB; k <<= 1) {
            const bool desc = ((tid & k) == 0);
            int j = k >> 1;
            for (; j >= 32; j >>= 1) {           // cross-warp: ping-pong smem
                float* K = buf ? kbuf1 : kbuf0;
                int*   I = buf ? ibuf1 : ibuf0;
                K[tid] = kt; I[tid] = idx;
                BAR256();
                int p = tid ^ j;
                float ok = K[p]; int oi = I[p];
                bool i_lower = ((tid & j) == 0);
                bool my_g = (kt > ok) || ((kt == ok) && (idx < oi));
                if (my_g != (i_lower == desc)) { kt = ok; idx = oi; }
                buf ^= 1;
            }
            for (; j > 0; j >>= 1) {             // intra-warp: shfl
                float ok = __shfl_xor_sync(0xffffffffu, kt, j);
                int   oi = __shfl_xor_sync(0xffffffffu, idx, j);
                bool i_lower = ((tid & j) == 0);
                bool my_g = (kt > ok) || ((kt == ok) && (idx < oi));
                if (my_g != (i_lower == desc)) { kt = ok; idx = oi; }
            }
        }
        BAR256();                 // sort exchanges done before se gather / wpart reuse

        st_s[tid] = kt;
        sidx[tid] = idx;

        // inclusive prefix sum of sorted e
        float v = se[idx];
        float x = v;
        #pragma unroll
        for (int off = 1; off < 32; off <<= 1) {
            float n = __shfl_up_sync(0xffffffffu, x, off);
            if (lane >= off) x += n;
        }
        if (lane == 31) wpart[wid] = x;
        BAR256();
        float woff = 0.f;
        for (int w = 0; w < wid; w++) woff += wpart[w];
        float pref = x + woff;

        g_tsrt[blk * RPB + tid] = kt;
        g_pe[blk * RPB + tid]   = pref;
    }

    grid_bar();    // single global sync: all chunks published

    // ================= Phase C: all 1024 threads =================
    // L2-coherent loads (__ldcg): g_tsrt/g_pe were written THIS kernel.
    #pragma unroll
    for (int i = tid; i < NB; i += NT)
        t_tab[(i >> 8) * TPAD + (i & 255)] = __ldcg(&g_tsrt[i]);
    __syncthreads();

    const int q   = tid >> 2;       // sorted position within block's chunk
    const int sub = tid & 3;
    const float ti = st_s[q];

    int cw[8];
    #pragma unroll
    for (int k = 0; k < 8; k++) cw[k] = 0;
    #pragma unroll
    for (int s = CHK / 2; s > 0; s >>= 1) {
        #pragma unroll
        for (int k = 0; k < 8; k++)
            cw[k] += (t_tab[(sub * 8 + k) * TPAD + cw[k] + s - 1] > ti) ? s : 0;
    }
    #pragma unroll
    for (int k = 0; k < 8; k++)
        cw[k] += (t_tab[(sub * 8 + k) * TPAD + cw[k]] > ti) ? 1 : 0;

    float sum = 0.f;
    int   cnt = 0;
    #pragma unroll
    for (int k = 0; k < 8; k++) {
        if (cw[k] > 0) {
            sum += __ldcg(&g_pe[(sub * 8 + k) * CHK + cw[k] - 1]);
            cnt += cw[k];
        }
    }
    sum += __shfl_xor_sync(0xffffffffu, sum, 1);
    sum += __shfl_xor_sync(0xffffffffu, sum, 2);
    cnt += __shfl_xor_sync(0xffffffffu, cnt, 1);
    cnt += __shfl_xor_sync(0xffffffffu, cnt, 2);

    float per = 0.f;
    int   cv  = 0;
    if (sub == 0) {
        int id = sidx[q];
        if ((sc[id] == 0) && (cnt > 0)) {
            per = __logf(sum) - srisk[id];
            cv  = 1;
        }
    }

    #pragma unroll
    for (int off = 16; off > 0; off >>= 1) {
        per += __shfl_xor_sync(0xffffffffu, per, off);
        cv  += __shfl_xor_sync(0xffffffffu, cv, off);
    }
    if (lane == 0) { bredf[wid] = per; bredi[wid] = cv; }
    __syncthreads();
    if (wid == 0) {
        float p2 = bredf[lane];
        int   c2 = bredi[lane];
        #pragma unroll
        for (int off = 16; off > 0; off >>= 1) {
            p2 += __shfl_xor_sync(0xffffffffu, p2, off);
            c2 += __shfl_xor_sync(0xffffffffu, c2, off);
        }
        if (lane == 0) {
            g_per[blk] = p2;
            g_cnt[blk] = c2;
            __threadfence();
            int tk = atomicAdd(&g_ticket, 1);
            is_last = (tk == GRID - 1) ? 1 : 0;
        }
    }
    __syncthreads();

    if (is_last && tid == 0) {
        __threadfence();      // acquire before reading other blocks' partials
        float per_t = 0.f, nll_t = 0.f;
        int cnt_t = 0;
        #pragma unroll
        for (int b = 0; b < GRID; b++) {
            per_t += __ldcg(&g_per[b]);
            cnt_t += __ldcg(&g_cnt[b]);
            nll_t += __ldcg(&g_nll[b]);
        }
        float rank = (cnt_t > 0) ? (per_t / (float)cnt_t) : 0.f;
        out[0] = nll_t / (float)NB + 0.5f * rank;
        g_ticket = 0;     // self-reset for graph replay
    }
}

extern "C" void kernel_launch(void* const* d_in, const int* in_sizes, int n_in,
                              void* d_out, int out_size)
{
    const float* outputs = (const float*)d_in[0];
    const int*   y       = (const int*)d_in[1];
    const float* t       = (const float*)d_in[2];
    const int*   c       = (const int*)d_in[3];
    float*       out     = (float*)d_out;

    surv_one_kernel<<<GRID, NT>>>(outputs, y, t, c, out);
}